// round 15
// baseline (speedup 1.0000x reference)
#include <cuda_runtime.h>
#include <cuda_fp16.h>
#include <cstdint>
#include <math.h>

// Problem constants
#define N_IMG 4
#define C_IN  256
#define HW    16384        // 128*128
#define MLP   128
#define NA    16
#define NB    64
#define ALPHA 300.0f

// ---------------------------------------------------------------------------
// SMEM layout (bytes)
//   w1 [o=128][k=256] fp16, pitch 528                 -> 67584
//   w2 [a=16][o=128]  fp16, pitch 272                 -> 4352
//   x  4-stage ring [k=16][p=128] fp32->fp16 inplace  -> 33792
//   PR (GEMM2 partial exchange) + Z live INSIDE the dead x ring.
//   b1 512, b2 64
// ---------------------------------------------------------------------------
#define W1_OFF   0
#define W2_OFF   67584
#define XS_OFF   71936
#define PR_OFF   XS_OFF                     // 16KB, ring slots 0-1 (dead)
#define Z_OFF    (XS_OFF + 16384)           // 9216B, slots 1-3 tail (dead by then)
#define B1S_OFF  105728
#define B2S_OFF  106240
#define SMEM_TOTAL 106304

#define W1_PITCH 528
#define W2_PITCH 272
#define XS_PITCH 528                  // fp32 row; fp16 packed into 16B per 32B chunk
#define XSTAGE_SZ (16 * XS_PITCH)     // 8448 per stage
#define Z_PITCH  72

__device__ __forceinline__ uint32_t smem_u32(const void* p) {
    uint32_t a;
    asm("{ .reg .u64 t; cvta.to.shared.u64 t, %1; cvt.u32.u64 %0, t; }" : "=r"(a) : "l"(p));
    return a;
}
__device__ __forceinline__ void ldsm_x4(uint32_t& r0, uint32_t& r1, uint32_t& r2, uint32_t& r3,
                                        uint32_t addr) {
    asm volatile("ldmatrix.sync.aligned.m8n8.x4.shared.b16 {%0,%1,%2,%3}, [%4];"
                 : "=r"(r0), "=r"(r1), "=r"(r2), "=r"(r3) : "r"(addr));
}
__device__ __forceinline__ void ldsm_x4_t(uint32_t& r0, uint32_t& r1, uint32_t& r2, uint32_t& r3,
                                          uint32_t addr) {
    asm volatile("ldmatrix.sync.aligned.m8n8.x4.trans.shared.b16 {%0,%1,%2,%3}, [%4];"
                 : "=r"(r0), "=r"(r1), "=r"(r2), "=r"(r3) : "r"(addr));
}
__device__ __forceinline__ void mma16816(float* c, const uint32_t* a, const uint32_t* b) {
    asm volatile(
        "mma.sync.aligned.m16n8k16.row.col.f32.f16.f16.f32 "
        "{%0,%1,%2,%3}, {%4,%5,%6,%7}, {%8,%9}, {%0,%1,%2,%3};"
        : "+f"(c[0]), "+f"(c[1]), "+f"(c[2]), "+f"(c[3])
        : "r"(a[0]), "r"(a[1]), "r"(a[2]), "r"(a[3]), "r"(b[0]), "r"(b[1]));
}
__device__ __forceinline__ uint32_t h2exp2_u(uint32_t arg) {
    uint32_t r;
    asm("ex2.approx.f16x2 %0, %1;" : "=r"(r) : "r"(arg));
    return r;
}
__device__ __forceinline__ uint32_t packh2(float a, float b) {
    __half2 h = __floats2half2_rn(a, b);
    return *(uint32_t*)&h;
}

// fp16 weights prepacked once (allocation-free: __device__ globals)
__device__ uint4 g_w1v[4096];    // w1 [o=128][k=256] halves, 8 per uint4
__device__ uint4 g_w2v[256];     // w2 [a=16][o=128]

__global__ void prep_kernel(const float* __restrict__ w1, const float* __restrict__ w2) {
    int i = blockIdx.x * 256 + threadIdx.x;     // 0..17407
    uint32_t* w1h = (uint32_t*)g_w1v;
    uint32_t* w2h = (uint32_t*)g_w2v;
    if (i < 16384) {
        float2 v = *(const float2*)(w1 + 2 * i);
        w1h[i] = packh2(v.x, v.y);
    } else {
        int j = i - 16384;
        float2 v = *(const float2*)(w2 + 2 * j);
        w2h[j] = packh2(v.x, v.y);
    }
}

extern __shared__ char smem[];

// ---------------------------------------------------------------------------
// Fused kernel, warp-pair o-split:
//   pair q (warps 2q,2q+1) owns px [32q,32q+32); even warp o[0:64], odd o[64:128].
//   x: cp.async.cg fp32 ring; each thread converts ITS OWN 32B chunk to fp16
//      in place after wait (no extra barrier). A frags via ldsm.x4.trans.
//   GEMM1 -> relu/pack -> GEMM2 partial (K=64) -> pair exchange via PR ->
//   softplus -> Z -> all-half2 attractor.
// ---------------------------------------------------------------------------
__global__ __launch_bounds__(256, 2) void fused_kernel(
    const float* __restrict__ x,
    const float* __restrict__ b1,
    const float* __restrict__ b2,
    const float* __restrict__ b_prev,
    float* __restrict__ out,
    int copies)
{
    const int tid = threadIdx.x;
    const int L   = tid & 31;
    const int wid = tid >> 5;
    const int pair = wid >> 1;
    const int par  = wid & 1;
    const int pix_base = blockIdx.x * 128;
    const int img = pix_base >> 14;
    const int hw0 = pix_base & (HW - 1);
    const uint32_t sb = smem_u32(smem);

    const float* xgb = x + (size_t)img * C_IN * HW + hw0;

    // ---- cp.async: thread owns 32B chunk (row cr, px [8*cm,8*cm+8)) ----
    const int cr = tid >> 4, cm = tid & 15;
    auto issue_stage = [&](int s) {
        uint32_t dst = sb + XS_OFF + (uint32_t)((s & 3) * XSTAGE_SZ + cr * XS_PITCH + cm * 32);
        const float* src = xgb + (size_t)(s * 16 + cr) * HW + cm * 8;
        asm volatile("cp.async.cg.shared.global [%0], [%1], 16;" :: "r"(dst), "l"(src) : "memory");
        asm volatile("cp.async.cg.shared.global [%0], [%1], 16;" :: "r"(dst + 16), "l"(src + 4) : "memory");
        asm volatile("cp.async.commit_group;" ::: "memory");
    };
    auto convert_stage = [&](int s) {           // own chunk: fp32 32B -> fp16 16B in place
        char* st = smem + XS_OFF + (s & 3) * XSTAGE_SZ + cr * XS_PITCH + cm * 32;
        float4 f0 = *(float4*)st;
        float4 f1 = *(float4*)(st + 16);
        uint4 h;
        h.x = packh2(f0.x, f0.y); h.y = packh2(f0.z, f0.w);
        h.z = packh2(f1.x, f1.y); h.w = packh2(f1.z, f1.w);
        *(uint4*)st = h;
    };

    issue_stage(0);
    issue_stage(1);
    issue_stage(2);

    // ---- stage weights + biases (overlaps with cp.async stages 0-2) ----
#pragma unroll
    for (int i = 0; i < 16; i++) {
        int idx = tid + i * 256;
        int o = idx >> 5, kq = idx & 31;
        *(uint4*)(smem + W1_OFF + o * W1_PITCH + kq * 16) = g_w1v[idx];
    }
    {
        int a = tid >> 4, kq = tid & 15;
        *(uint4*)(smem + W2_OFF + a * W2_PITCH + kq * 16) = g_w2v[tid];
        if (tid < 128) ((float*)(smem + B1S_OFF))[tid] = b1[tid];
        if (tid < 16)  ((float*)(smem + B2S_OFF))[tid] = b2[tid];
    }

    asm volatile("cp.async.wait_group 2;" ::: "memory");   // own stage-0 chunk done
    convert_stage(0);
    __syncthreads();                                        // all fp16(0) + weights visible

    // ---- GEMM1: acc[ot 4][mt 2][nt 2][4]: px32 x o64 per warp ----
    const int p0  = pair * 32;
    const int w1o = par * 64;
    float acc[4][2][2][4];
#pragma unroll
    for (int ot = 0; ot < 4; ot++)
#pragma unroll
        for (int mt = 0; mt < 2; mt++)
#pragma unroll
            for (int nt = 0; nt < 2; nt++)
#pragma unroll
                for (int j = 0; j < 4; j++) acc[ot][mt][nt][j] = 0.0f;

    const uint32_t w_row  = (uint32_t)((L & 7) + ((L >> 4) << 3));
    const uint32_t w_colo = (uint32_t)(((L >> 3) & 1) << 3);
    const uint32_t w1ls_warp = sb + W1_OFF + (w1o + w_row) * W1_PITCH + w_colo * 2;
    const uint32_t w2ls_base = sb + W2_OFF + w_row * W2_PITCH + w_colo * 2;
    // A ldsm.trans: lane -> k-row (L&15), px-seg (L>>4)
    const uint32_t als_base = sb + XS_OFF + (uint32_t)((L & 15) * XS_PITCH + (L >> 4) * 32);

#pragma unroll
    for (int s = 0; s < 16; s++) {
        if (s + 3 < 16) issue_stage(s + 3);

        uint32_t sbase = als_base + (uint32_t)((s & 3) * XSTAGE_SZ);
        uint32_t t0, t1, t2, t3;
        ldsm_x4_t(t0, t1, t2, t3, sbase + (uint32_t)((p0 >> 3) * 32));
        uint32_t af0[4] = {t0, t2, t1, t3};
        ldsm_x4_t(t0, t1, t2, t3, sbase + (uint32_t)(((p0 + 16) >> 3) * 32));
        uint32_t af1[4] = {t0, t2, t1, t3};

#pragma unroll
        for (int ot = 0; ot < 4; ot++) {
            uint32_t bw[4];
            ldsm_x4(bw[0], bw[1], bw[2], bw[3],
                    w1ls_warp + (uint32_t)(ot * 16) * W1_PITCH + (uint32_t)(s * 16) * 2);
            mma16816(acc[ot][0][0], af0, bw);
            mma16816(acc[ot][0][1], af0, bw + 2);
            mma16816(acc[ot][1][0], af1, bw);
            mma16816(acc[ot][1][1], af1, bw + 2);
        }

        if (s < 15) {
            if (s <= 12)      { asm volatile("cp.async.wait_group 2;" ::: "memory"); }
            else if (s == 13) { asm volatile("cp.async.wait_group 1;" ::: "memory"); }
            else              { asm volatile("cp.async.wait_group 0;" ::: "memory"); }
            convert_stage(s + 1);
            __syncthreads();
        }
    }

    // ---- epilogue1: +b1, relu, pack -> h2r[mt][16] (A2 frags, k = o-local) ----
    uint32_t h2r[2][16];
    {
        const float2* b1f2 = (const float2*)(smem + B1S_OFF);
#pragma unroll
        for (int ot = 0; ot < 4; ot++)
#pragma unroll
            for (int ntl = 0; ntl < 2; ntl++) {
                int j = ot * 2 + ntl;
                float2 bb = b1f2[w1o / 2 + j * 4 + (L & 3)];
#pragma unroll
                for (int mt = 0; mt < 2; mt++) {
                    float v0 = fmaxf(acc[ot][mt][ntl][0] + bb.x, 0.0f);
                    float v1 = fmaxf(acc[ot][mt][ntl][1] + bb.y, 0.0f);
                    float v2 = fmaxf(acc[ot][mt][ntl][2] + bb.x, 0.0f);
                    float v3 = fmaxf(acc[ot][mt][ntl][3] + bb.y, 0.0f);
                    h2r[mt][2 * j]     = packh2(v0, v1);
                    h2r[mt][2 * j + 1] = packh2(v2, v3);
                }
            }
    }

    // ---- GEMM2 partial: K = o-half = 64 (4 ksteps) ----
    float zacc[2][2][4];
#pragma unroll
    for (int mt = 0; mt < 2; mt++)
#pragma unroll
        for (int nt = 0; nt < 2; nt++)
#pragma unroll
            for (int j = 0; j < 4; j++) zacc[mt][nt][j] = 0.0f;

#pragma unroll
    for (int s2 = 0; s2 < 4; s2++) {
        uint32_t bw[4];
        ldsm_x4(bw[0], bw[1], bw[2], bw[3], w2ls_base + (uint32_t)((w1o + s2 * 16) * 2));
        mma16816(zacc[0][0], &h2r[0][4 * s2], bw);
        mma16816(zacc[0][1], &h2r[0][4 * s2], bw + 2);
        mma16816(zacc[1][0], &h2r[1][4 * s2], bw);
        mma16816(zacc[1][1], &h2r[1][4 * s2], bw + 2);
    }

    // ---- pair exchange via PR (ring slots 0-1, dead) ----
    {
        char* pr = smem + PR_OFF + pair * 4096 + par * 2048 + L * 64;
        *(float4*)(pr)      = *(float4*)zacc[0][0];
        *(float4*)(pr + 16) = *(float4*)zacc[0][1];
        *(float4*)(pr + 32) = *(float4*)zacc[1][0];
        *(float4*)(pr + 48) = *(float4*)zacc[1][1];
    }
    __syncthreads();   // also guarantees all warps done with x ring (stage 15)

    // ---- each warp: mt = par; sum partials, +b2, softplus, store Z ----
    {
        const float2* b2f2 = (const float2*)(smem + B2S_OFF);
        const char* pe = smem + PR_OFF + pair * 4096 +        L * 64 + par * 32;
        const char* po = smem + PR_OFF + pair * 4096 + 2048 + L * 64 + par * 32;
        float4 e0 = *(const float4*)pe, e1 = *(const float4*)(pe + 16);
        float4 q0 = *(const float4*)po, q1 = *(const float4*)(po + 16);
        float z0[4] = {e0.x + q0.x, e0.y + q0.y, e0.z + q0.z, e0.w + q0.w};
        float z1[4] = {e1.x + q1.x, e1.y + q1.y, e1.z + q1.z, e1.w + q1.w};
        const int px = p0 + par * 16 + (L >> 2);
        const int ac = 2 * (L & 3);
        char* zb = smem + Z_OFF;
#pragma unroll
        for (int nt = 0; nt < 2; nt++) {
            float* zp = nt ? z1 : z0;
            float2 bb = b2f2[nt * 4 + (L & 3)];
            float v0 = zp[0] + bb.x, v1 = zp[1] + bb.y;
            float v2 = zp[2] + bb.x, v3 = zp[3] + bb.y;
            float s0 = fmaxf(v0, 0.0f) + log1pf(__expf(-fabsf(v0)));
            float s1 = fmaxf(v1, 0.0f) + log1pf(__expf(-fabsf(v1)));
            float s2 = fmaxf(v2, 0.0f) + log1pf(__expf(-fabsf(v2)));
            float s3 = fmaxf(v3, 0.0f) + log1pf(__expf(-fabsf(v3)));
            *(float2*)(zb + (size_t)px * Z_PITCH + (nt * 8 + ac) * 4)       = make_float2(s0, s1);
            *(float2*)(zb + (size_t)(px + 8) * Z_PITCH + (nt * 8 + ac) * 4) = make_float2(s2, s3);
        }
    }
    __syncthreads();

    // ---- attractor: warp w -> px [16w,16w+16), 2 lanes/px, 32 bins each ----
    {
        const char* warpz = smem + Z_OFF + wid * (16 * Z_PITCH);
        const int px_l = L & 15;
        const int half = L >> 4;
        const float* zr = (const float*)(warpz + (size_t)px_l * Z_PITCH);
        uint32_t AvH2[8];
#pragma unroll
        for (int q = 0; q < 8; q++) {
            float2 v = *(const float2*)(zr + 2 * q);
            AvH2[q] = packh2(v.x, v.y);
        }

        const int gpix = hw0 + wid * 16 + px_l;
        const float* bp = b_prev + (size_t)img * NB * HW + gpix + (size_t)(half * 32) * HW;
        float* o0 = out + (size_t)img * NB * HW + gpix + (size_t)(half * 32) * HW;
        float* o1 = o0 + (size_t)N_IMG * NB * HW;
        const __half2 KH2 = __float2half2_rn(-432.80852f);   // -ALPHA * log2(e)

        float bcv[2][8];
#pragma unroll
        for (int j = 0; j < 8; j++)
            bcv[0][j] = bp[(size_t)j * HW];

        for (int c = 0; c < 4; c++) {
            const int cur = c & 1, nxt = cur ^ 1;
            if (c < 3) {
#pragma unroll
                for (int j = 0; j < 8; j++)
                    bcv[nxt][j] = bp[(size_t)((c + 1) * 8 + j) * HW];
            }
            float rv[8];
#pragma unroll
            for (int j = 0; j < 8; j++) {
                float bc = bcv[cur][j];
                __half2 bch = __float2half2_rn(bc);
                __half2 dh0 = __hsub2(*(const __half2*)&AvH2[0], bch);
                __half2 ar0 = __hmul2(__hmul2(dh0, dh0), KH2);
                uint32_t e0 = h2exp2_u(*(uint32_t*)&ar0);
                __half2 accA = __hmul2(*(__half2*)&e0, dh0);
                __half2 dh1 = __hsub2(*(const __half2*)&AvH2[1], bch);
                __half2 ar1 = __hmul2(__hmul2(dh1, dh1), KH2);
                uint32_t e1 = h2exp2_u(*(uint32_t*)&ar1);
                __half2 accB = __hmul2(*(__half2*)&e1, dh1);
#pragma unroll
                for (int i = 2; i < 8; i += 2) {
                    __half2 dha = __hsub2(*(const __half2*)&AvH2[i], bch);
                    __half2 ara = __hmul2(__hmul2(dha, dha), KH2);
                    uint32_t ea = h2exp2_u(*(uint32_t*)&ara);
                    accA = __hfma2(*(__half2*)&ea, dha, accA);
                    __half2 dhb = __hsub2(*(const __half2*)&AvH2[i + 1], bch);
                    __half2 arb = __hmul2(__hmul2(dhb, dhb), KH2);
                    uint32_t eb = h2exp2_u(*(uint32_t*)&arb);
                    accB = __hfma2(*(__half2*)&eb, dhb, accB);
                }
                float2 fa = __half22float2(accA);
                float2 fb = __half22float2(accB);
                rv[j] = bc + ((fa.x + fa.y) + (fb.x + fb.y));
            }
#pragma unroll
            for (int j = 0; j < 8; j++) {
                o0[(size_t)(c * 8 + j) * HW] = rv[j];
                if (copies >= 2) o1[(size_t)(c * 8 + j) * HW] = rv[j];
            }
        }
    }
}

// ---------------------------------------------------------------------------
// Launch. Inputs (metadata order): x, b_prev, w1, b1, w2, b2.
// ---------------------------------------------------------------------------
extern "C" void kernel_launch(void* const* d_in, const int* in_sizes, int n_in,
                              void* d_out, int out_size) {
    const float* x      = (const float*)d_in[0];
    const float* b_prev = (const float*)d_in[1];
    const float* w1     = (const float*)d_in[2];
    const float* b1     = (const float*)d_in[3];
    const float* w2     = (const float*)d_in[4];
    const float* b2     = (const float*)d_in[5];
    float* out = (float*)d_out;

    const int one_out = N_IMG * NB * HW;
    int copies = out_size / one_out;

    static bool attr_set = false;
    if (!attr_set) {
        cudaFuncSetAttribute(fused_kernel,
                             cudaFuncAttributeMaxDynamicSharedMemorySize, SMEM_TOTAL);
        attr_set = true;
    }

    prep_kernel<<<68, 256>>>(w1, w2);
    fused_kernel<<<(N_IMG * HW) / 128, 256, SMEM_TOTAL>>>(
        x, b1, b2, b_prev, out, copies);
}

// round 16
// speedup vs baseline: 1.2065x; 1.2065x over previous
#include <cuda_runtime.h>
#include <cuda_fp16.h>
#include <cstdint>
#include <math.h>

// Problem constants
#define N_IMG 4
#define C_IN  256
#define HW    16384        // 128*128
#define MLP   128
#define NA    16
#define NB    64
#define ALPHA 300.0f

// ---------------------------------------------------------------------------
// SMEM layout (bytes)  — identical to the 39.4us kernel
//   w1 [o=128][k=256] fp16, pitch 528                 -> 67584
//   w2 [a=16][o=128]  fp16, pitch 272                 -> 4352
//   x  4-stage ring [k=16][p=128] fp32, pitch 528     -> 33792
//   z  per-warp [p=16][a=16] f32, pitch 72            -> 9216 (separate region)
//   b1 512, b2 64
// ---------------------------------------------------------------------------
#define W1_OFF   0
#define W2_OFF   67584
#define XS_OFF   71936
#define Z_OFF    105728
#define B1S_OFF  114944
#define B2S_OFF  115456
#define SMEM_TOTAL 115520

#define W1_PITCH 528
#define W2_PITCH 272
#define XS_PITCH 528                  // 132 floats per k-row
#define XSTAGE_SZ (16 * XS_PITCH)     // 8448 per stage
#define Z_PITCH  72

__device__ __forceinline__ uint32_t smem_u32(const void* p) {
    uint32_t a;
    asm("{ .reg .u64 t; cvta.to.shared.u64 t, %1; cvt.u32.u64 %0, t; }" : "=r"(a) : "l"(p));
    return a;
}
__device__ __forceinline__ void ldsm_x4(uint32_t& r0, uint32_t& r1, uint32_t& r2, uint32_t& r3,
                                        uint32_t addr) {
    asm volatile("ldmatrix.sync.aligned.m8n8.x4.shared.b16 {%0,%1,%2,%3}, [%4];"
                 : "=r"(r0), "=r"(r1), "=r"(r2), "=r"(r3) : "r"(addr));
}
__device__ __forceinline__ void mma16816(float* c, const uint32_t* a, const uint32_t* b) {
    asm volatile(
        "mma.sync.aligned.m16n8k16.row.col.f32.f16.f16.f32 "
        "{%0,%1,%2,%3}, {%4,%5,%6,%7}, {%8,%9}, {%0,%1,%2,%3};"
        : "+f"(c[0]), "+f"(c[1]), "+f"(c[2]), "+f"(c[3])
        : "r"(a[0]), "r"(a[1]), "r"(a[2]), "r"(a[3]), "r"(b[0]), "r"(b[1]));
}
__device__ __forceinline__ uint32_t h2exp2_u(uint32_t arg) {
    uint32_t r;
    asm("ex2.approx.f16x2 %0, %1;" : "=r"(r) : "r"(arg));
    return r;
}
__device__ __forceinline__ uint32_t packh2(float a, float b) {
    __half2 h = __floats2half2_rn(a, b);
    return *(uint32_t*)&h;
}

// fp16 weights prepacked once (allocation-free: __device__ globals)
__device__ uint4 g_w1v[4096];    // w1 [o=128][k=256] halves, 8 per uint4
__device__ uint4 g_w2v[256];     // w2 [a=16][o=128]

// Fast prep: 68 blocks x 256 thr, one float2 -> half2 per thread (coalesced).
__global__ void prep_kernel(const float* __restrict__ w1, const float* __restrict__ w2) {
    int i = blockIdx.x * 256 + threadIdx.x;     // 0..17407
    uint32_t* w1h = (uint32_t*)g_w1v;
    uint32_t* w2h = (uint32_t*)g_w2v;
    if (i < 16384) {
        float2 v = *(const float2*)(w1 + 2 * i);
        w1h[i] = packh2(v.x, v.y);
    } else {
        int j = i - 16384;
        float2 v = *(const float2*)(w2 + 2 * j);
        w2h[j] = packh2(v.x, v.y);
    }
}

extern __shared__ char smem[];

// ---------------------------------------------------------------------------
// Persistent 2-tile fused kernel (grid 256; CTA processes tiles bid, bid+256).
// Per tile: x cp.async ring (depth 3) -> GEMM1 -> relu/pack -> GEMM2 ->
// softplus -> warp-local z -> all-half2 attractor. Weights staged ONCE.
// Tile t+1's first 3 x-stages are issued during tile t's attract phase
// (ring slots 0-2 provably dead there; Z lives outside the ring).
// ---------------------------------------------------------------------------
__global__ __launch_bounds__(256, 2) void fused_kernel(
    const float* __restrict__ x,
    const float* __restrict__ b1,
    const float* __restrict__ b2,
    const float* __restrict__ b_prev,
    float* __restrict__ out,
    int copies)
{
    const int tid = threadIdx.x;
    const int L   = tid & 31;
    const int wid = tid >> 5;
    const uint32_t sb = smem_u32(smem);

    // cp.async chunk mapping (2 x 16B per thread per stage)
    const int c0r = tid >> 5,          c0q = tid & 31;
    const int c1r = (tid + 256) >> 5,  c1q = tid & 31;
    auto issue_stage = [&](const float* xgb_, int s) {
        uint32_t dst = sb + XS_OFF + (uint32_t)((s & 3) * XSTAGE_SZ);
        const float* s0 = xgb_ + (size_t)(s * 16 + c0r) * HW + c0q * 4;
        const float* s1 = xgb_ + (size_t)(s * 16 + c1r) * HW + c1q * 4;
        asm volatile("cp.async.cg.shared.global [%0], [%1], 16;"
                     :: "r"(dst + (uint32_t)(c0r * XS_PITCH + c0q * 16)), "l"(s0) : "memory");
        asm volatile("cp.async.cg.shared.global [%0], [%1], 16;"
                     :: "r"(dst + (uint32_t)(c1r * XS_PITCH + c1q * 16)), "l"(s1) : "memory");
        asm volatile("cp.async.commit_group;" ::: "memory");
    };

    // per-tile x base pointers
    const int pb0 = blockIdx.x * 128;
    const int pb1 = (blockIdx.x + 256) * 128;
    const float* xgb0 = x + (size_t)(pb0 >> 14) * C_IN * HW + (pb0 & (HW - 1));
    const float* xgb1 = x + (size_t)(pb1 >> 14) * C_IN * HW + (pb1 & (HW - 1));

    // lane-derived constants (tile-invariant)
    const int p0 = wid * 16;
    const int g  = L >> 2;
    const int t2 = (L & 3) * 2;
    const uint32_t w_row  = (uint32_t)((L & 7) + ((L >> 4) << 3));
    const uint32_t w_colo = (uint32_t)(((L >> 3) & 1) << 3);
    const uint32_t w1ls_base = sb + W1_OFF + w_row * W1_PITCH + w_colo * 2;
    const uint32_t w2ls_base = sb + W2_OFF + w_row * W2_PITCH + w_colo * 2;

    // ---- tile-0 prologue: x stages + one-time weight staging ----
    issue_stage(xgb0, 0);
    issue_stage(xgb0, 1);
    issue_stage(xgb0, 2);

#pragma unroll
    for (int i = 0; i < 16; i++) {
        int idx = tid + i * 256;             // 0..4095
        int o = idx >> 5, kq = idx & 31;
        *(uint4*)(smem + W1_OFF + o * W1_PITCH + kq * 16) = g_w1v[idx];
    }
    {
        int a = tid >> 4, kq = tid & 15;
        *(uint4*)(smem + W2_OFF + a * W2_PITCH + kq * 16) = g_w2v[tid];
        if (tid < 128) ((float*)(smem + B1S_OFF))[tid] = b1[tid];
        if (tid < 16)  ((float*)(smem + B2S_OFF))[tid] = b2[tid];
    }

#pragma unroll 1
    for (int t = 0; t < 2; t++) {
        const int pix_base = t ? pb1 : pb0;
        const float* xgb = t ? xgb1 : xgb0;
        const int img = pix_base >> 14;
        const int hw0 = pix_base & (HW - 1);

        asm volatile("cp.async.wait_group 2;" ::: "memory");   // stage 0 done
        __syncthreads();                                        // visible to all

        // ---- GEMM1: C[p16][o128] in regs, 16 k-steps, prefetch depth 3 ----
        float acc[16][4];
#pragma unroll
        for (int nt = 0; nt < 16; nt++)
#pragma unroll
            for (int j = 0; j < 4; j++) acc[nt][j] = 0.0f;

#pragma unroll
        for (int s = 0; s < 16; s++) {
            if (s + 3 < 16) issue_stage(xgb, s + 3);

            const float* xb = (const float*)(smem + XS_OFF + (s & 3) * XSTAGE_SZ);
            const float* pc  = xb + p0 + g;
            const float* pc8 = pc + 8;
            uint32_t af[4];
            af[0] = packh2(pc [ t2      * 132], pc [(t2 + 1) * 132]);
            af[1] = packh2(pc8[ t2      * 132], pc8[(t2 + 1) * 132]);
            af[2] = packh2(pc [(t2 + 8) * 132], pc [(t2 + 9) * 132]);
            af[3] = packh2(pc8[(t2 + 8) * 132], pc8[(t2 + 9) * 132]);

#pragma unroll
            for (int nt2 = 0; nt2 < 8; nt2++) {
                uint32_t bw[4];
                ldsm_x4(bw[0], bw[1], bw[2], bw[3],
                        w1ls_base + (uint32_t)(nt2 * 16) * W1_PITCH + (uint32_t)(s * 16) * 2);
                mma16816(acc[2 * nt2],     af, bw);
                mma16816(acc[2 * nt2 + 1], af, bw + 2);
            }

            if (s < 15) {
                if (s <= 12)      { asm volatile("cp.async.wait_group 2;" ::: "memory"); }
                else if (s == 13) { asm volatile("cp.async.wait_group 1;" ::: "memory"); }
                else              { asm volatile("cp.async.wait_group 0;" ::: "memory"); }
                __syncthreads();
            }
        }

        // ---- epilogue1: +b1, relu, pack fp16 -> A2 frags in regs ----
        uint32_t h2r[32];
        {
            const float2* b1f2 = (const float2*)(smem + B1S_OFF);
#pragma unroll
            for (int nt = 0; nt < 16; nt++) {
                float2 bb = b1f2[nt * 4 + (L & 3)];
                float v0 = fmaxf(acc[nt][0] + bb.x, 0.0f);
                float v1 = fmaxf(acc[nt][1] + bb.y, 0.0f);
                float v2 = fmaxf(acc[nt][2] + bb.x, 0.0f);
                float v3 = fmaxf(acc[nt][3] + bb.y, 0.0f);
                h2r[2 * nt]     = packh2(v0, v1);
                h2r[2 * nt + 1] = packh2(v2, v3);
            }
        }

        // ---- GEMM2: z[p16][a16], K = 128 (8 ksteps), A = h2r in regs ----
        float zacc[2][4];
#pragma unroll
        for (int nt = 0; nt < 2; nt++)
#pragma unroll
            for (int j = 0; j < 4; j++) zacc[nt][j] = 0.0f;

#pragma unroll
        for (int s2 = 0; s2 < 8; s2++) {
            uint32_t bw[4];
            ldsm_x4(bw[0], bw[1], bw[2], bw[3], w2ls_base + (uint32_t)(s2 * 16) * 2);
            mma16816(zacc[0], &h2r[4 * s2], bw);
            mma16816(zacc[1], &h2r[4 * s2], bw + 2);
        }

        // ---- +b2, softplus (fast __logf) -> warp-local z smem [p16][a16] ----
        char* warpz = smem + Z_OFF + wid * (16 * Z_PITCH);
        {
            const float2* b2f2 = (const float2*)(smem + B2S_OFF);
            int lrow = L >> 2;
            int acol = 2 * (L & 3);
#pragma unroll
            for (int nt = 0; nt < 2; nt++) {
                float2 bb = b2f2[nt * 4 + (L & 3)];
                float z0 = zacc[nt][0] + bb.x;
                float z1 = zacc[nt][1] + bb.y;
                float z2 = zacc[nt][2] + bb.x;
                float z3 = zacc[nt][3] + bb.y;
                float s0  = fmaxf(z0, 0.0f) + __logf(1.0f + __expf(-fabsf(z0)));
                float s1  = fmaxf(z1, 0.0f) + __logf(1.0f + __expf(-fabsf(z1)));
                float s2v = fmaxf(z2, 0.0f) + __logf(1.0f + __expf(-fabsf(z2)));
                float s3  = fmaxf(z3, 0.0f) + __logf(1.0f + __expf(-fabsf(z3)));
                *(float2*)(warpz + (size_t)lrow * Z_PITCH + (nt * 8 + acol) * 4)
                    = make_float2(s0, s1);
                *(float2*)(warpz + (size_t)(lrow + 8) * Z_PITCH + (nt * 8 + acol) * 4)
                    = make_float2(s2v, s3);
            }
        }
        __syncwarp();

        // ---- attractor: 2 lanes per pixel (16 px), 32 bins each ----
        {
            const int px_l = L & 15;
            const int half = L >> 4;
            const float* zr = (const float*)(warpz + (size_t)px_l * Z_PITCH);
            uint32_t AvH2[8];
#pragma unroll
            for (int q = 0; q < 8; q++) {
                float2 v = *(const float2*)(zr + 2 * q);
                AvH2[q] = packh2(v.x, v.y);
            }

            // prefetch next tile's first x stages into dead ring slots 0-2
            // (all warps have passed the s=14 barrier; slot 3 untouched)
            if (t == 0) {
                issue_stage(xgb1, 0);
                issue_stage(xgb1, 1);
                issue_stage(xgb1, 2);
            }

            const int gpix = hw0 + p0 + px_l;
            const float* bp = b_prev + (size_t)img * NB * HW + gpix + (size_t)(half * 32) * HW;
            float* o0 = out + (size_t)img * NB * HW + gpix + (size_t)(half * 32) * HW;
            float* o1 = o0 + (size_t)N_IMG * NB * HW;
            const __half2 KH2 = __float2half2_rn(-432.80852f);   // -ALPHA * log2(e)

            float bcv[2][8];
#pragma unroll
            for (int j = 0; j < 8; j++)
                bcv[0][j] = bp[(size_t)j * HW];

            for (int c = 0; c < 4; c++) {            // 4 chunks x 8 bins
                const int cur = c & 1, nxt = cur ^ 1;
                if (c < 3) {
#pragma unroll
                    for (int j = 0; j < 8; j++)
                        bcv[nxt][j] = bp[(size_t)((c + 1) * 8 + j) * HW];
                }
                float rv[8];
#pragma unroll
                for (int j = 0; j < 8; j++) {
                    float bc = bcv[cur][j];
                    __half2 bch = __float2half2_rn(bc);
                    __half2 dh0 = __hsub2(*(const __half2*)&AvH2[0], bch);
                    __half2 ar0 = __hmul2(__hmul2(dh0, dh0), KH2);
                    uint32_t e0 = h2exp2_u(*(uint32_t*)&ar0);
                    __half2 accA = __hmul2(*(__half2*)&e0, dh0);
                    __half2 dh1 = __hsub2(*(const __half2*)&AvH2[1], bch);
                    __half2 ar1 = __hmul2(__hmul2(dh1, dh1), KH2);
                    uint32_t e1 = h2exp2_u(*(uint32_t*)&ar1);
                    __half2 accB = __hmul2(*(__half2*)&e1, dh1);
#pragma unroll
                    for (int i = 2; i < 8; i += 2) {
                        __half2 dha = __hsub2(*(const __half2*)&AvH2[i], bch);
                        __half2 ara = __hmul2(__hmul2(dha, dha), KH2);
                        uint32_t ea = h2exp2_u(*(uint32_t*)&ara);
                        accA = __hfma2(*(__half2*)&ea, dha, accA);
                        __half2 dhb = __hsub2(*(const __half2*)&AvH2[i + 1], bch);
                        __half2 arb = __hmul2(__hmul2(dhb, dhb), KH2);
                        uint32_t eb = h2exp2_u(*(uint32_t*)&arb);
                        accB = __hfma2(*(__half2*)&eb, dhb, accB);
                    }
                    float2 fa = __half22float2(accA);
                    float2 fb = __half22float2(accB);
                    rv[j] = bc + ((fa.x + fa.y) + (fb.x + fb.y));
                }
#pragma unroll
                for (int j = 0; j < 8; j++) {
                    o0[(size_t)(c * 8 + j) * HW] = rv[j];
                    if (copies >= 2) o1[(size_t)(c * 8 + j) * HW] = rv[j];
                }
            }
        }
    }
}

// ---------------------------------------------------------------------------
// Launch. Inputs (metadata order): x, b_prev, w1, b1, w2, b2.
// ---------------------------------------------------------------------------
extern "C" void kernel_launch(void* const* d_in, const int* in_sizes, int n_in,
                              void* d_out, int out_size) {
    const float* x      = (const float*)d_in[0];
    const float* b_prev = (const float*)d_in[1];
    const float* w1     = (const float*)d_in[2];
    const float* b1     = (const float*)d_in[3];
    const float* w2     = (const float*)d_in[4];
    const float* b2     = (const float*)d_in[5];
    float* out = (float*)d_out;

    const int one_out = N_IMG * NB * HW;
    int copies = out_size / one_out;

    static bool attr_set = false;
    if (!attr_set) {
        cudaFuncSetAttribute(fused_kernel,
                             cudaFuncAttributeMaxDynamicSharedMemorySize, SMEM_TOTAL);
        attr_set = true;
    }

    prep_kernel<<<68, 256>>>(w1, w2);
    fused_kernel<<<256, 256, SMEM_TOTAL>>>(x, b1, b2, b_prev, out, copies);
}